// round 10
// baseline (speedup 1.0000x reference)
#include <cuda_runtime.h>
#include <math.h>
#include <stdint.h>

#define NBATCH 64
#define NSTEP  1024
#define NIN    256
#define NH     512

#define WROW 516  // padded k-stride (floats): conflict-free LDS.128 on weight rows
// smem floats: weights [3][32][WROW] | union(hsm 16KB / part 24KB) | h_pub[2][256] | mbar[16]
#define UN_OFF    (3*32*WROW)
#define PUB_OFF   (UN_OFF + 8*768)
#define MBAR_OFFB ((PUB_OFF + 512)*4)          // byte offset of mbarriers
#define SMEM_BYTES (MBAR_OFFB + 16*8)

typedef unsigned long long u64;

// packed fp32x2 FMA — SASS FFMA2
#define FMA2(acc, a, b) asm("fma.rn.f32x2 %0, %1, %2, %0;" : "+l"(acc) : "l"(a), "l"(b))
#define DUP2(r, x)      asm("mov.b64 %0, {%1, %1};" : "=l"(r) : "f"(x))
#define UNPACK2(lo, hi, v) asm("mov.b64 {%0, %1}, %2;" : "=f"(lo), "=f"(hi) : "l"(v))

__device__ float g_x[(size_t)3*NBATCH*NSTEP*NH];   // ~403 MB input projections

__device__ __forceinline__ uint32_t smem_u32(const void* p) {
  uint32_t a;
  asm("{ .reg .u64 t; cvta.to.shared.u64 t, %1; cvt.u32.u64 %0, t; }" : "=r"(a) : "l"(p));
  return a;
}

// ---------------- input projection GEMM ----------------
__global__ void __launch_bounds__(256) xproj_kernel(
    const float* __restrict__ A,
    const float* __restrict__ w0, const float* __restrict__ w1, const float* __restrict__ w2,
    const float* __restrict__ b0, const float* __restrict__ b1, const float* __restrict__ b2)
{
  __shared__ float As[32][68];
  __shared__ float Bs[32][68];

  int tid = threadIdx.x;
  int g = blockIdx.z;
  const float* W    = (g==0) ? w0 : ((g==1) ? w1 : w2);
  const float* bias = (g==0) ? b0 : ((g==1) ? b1 : b2);
  float* C = g_x + (size_t)g * (size_t)(NBATCH*NSTEP) * NH;

  int m0 = blockIdx.y * 64;
  int n0 = blockIdx.x * 64;
  int tx = tid & 15, ty = tid >> 4;
  int lr = tid >> 3;
  int lc = (tid & 7) * 4;

  u64 acc2[4][2] = {};

  for (int k0 = 0; k0 < NIN; k0 += 32) {
    float4 a0 = *(const float4*)(A + (size_t)(m0+lr   )*NIN + k0 + lc);
    float4 a1 = *(const float4*)(A + (size_t)(m0+lr+32)*NIN + k0 + lc);
    float4 v0 = *(const float4*)(W + (size_t)(n0+lr   )*NIN + k0 + lc);
    float4 v1 = *(const float4*)(W + (size_t)(n0+lr+32)*NIN + k0 + lc);
    __syncthreads();
    As[lc+0][lr] = a0.x; As[lc+1][lr] = a0.y; As[lc+2][lr] = a0.z; As[lc+3][lr] = a0.w;
    As[lc+0][lr+32] = a1.x; As[lc+1][lr+32] = a1.y; As[lc+2][lr+32] = a1.z; As[lc+3][lr+32] = a1.w;
    Bs[lc+0][lr] = v0.x; Bs[lc+1][lr] = v0.y; Bs[lc+2][lr] = v0.z; Bs[lc+3][lr] = v0.w;
    Bs[lc+0][lr+32] = v1.x; Bs[lc+1][lr+32] = v1.y; Bs[lc+2][lr+32] = v1.z; Bs[lc+3][lr+32] = v1.w;
    __syncthreads();
    #pragma unroll
    for (int kk = 0; kk < 32; kk++) {
      float4 av = *(const float4*)(&As[kk][ty*4]);
      ulonglong2 bp = *(const ulonglong2*)(&Bs[kk][tx*4]);
      u64 d0, d1, d2, d3;
      DUP2(d0, av.x); DUP2(d1, av.y); DUP2(d2, av.z); DUP2(d3, av.w);
      FMA2(acc2[0][0], d0, bp.x); FMA2(acc2[0][1], d0, bp.y);
      FMA2(acc2[1][0], d1, bp.x); FMA2(acc2[1][1], d1, bp.y);
      FMA2(acc2[2][0], d2, bp.x); FMA2(acc2[2][1], d2, bp.y);
      FMA2(acc2[3][0], d3, bp.x); FMA2(acc2[3][1], d3, bp.y);
    }
  }

  float4 bv = *(const float4*)(bias + n0 + tx*4);
  #pragma unroll
  for (int i = 0; i < 4; i++) {
    int row = m0 + ty*4 + i;
    float c0, c1, c2, c3;
    UNPACK2(c0, c1, acc2[i][0]);
    UNPACK2(c2, c3, acc2[i][1]);
    float4 o;
    o.x = c0 + bv.x; o.y = c1 + bv.y;
    o.z = c2 + bv.z; o.w = c3 + bv.w;
    *(float4*)(C + (size_t)row*NH + n0 + tx*4) = o;
  }
}

// ---------------- persistent GRU recurrence: 16-CTA clusters + DSMEM handshake --------
// grid = 128 CTAs = 8 clusters of 16 (cluster c = batch group c; ctarank jt = j-tile).
// CTA (bgrp, jt) owns batches [bgrp*8,+8) x cols [jt*32,+32), all 3 gates; weights in smem.
// Per step: producers write their 256-float chunk into own-smem h_pub[t&1] and arrive
// (release.cluster) on mbar[jt] of every cluster CTA; consumer warp r try_waits
// (acquire.cluster) on local mbar[r], pulls 1KB from producer r's smem via mapa+
// ld.shared::cluster, stages into hsm, runs its k-slice matvec. No L2 traffic for h.
__global__ void __launch_bounds__(512, 1) gru_rec(
    const float* __restrict__ h0,
    const float* __restrict__ w_hr, const float* __restrict__ w_hz, const float* __restrict__ w_hn,
    const float* __restrict__ b_hr, const float* __restrict__ b_hz, const float* __restrict__ b_hn,
    float* __restrict__ out, int write_hlast)
{
  extern __shared__ float sm[];
  float* wsm   = sm;                   // [3][32][WROW]
  float* un    = sm + UN_OFF;          // union: hsm [8][512] / part [8][768]
  float* hsm   = un;
  float* part  = un;
  float* h_pub = sm + PUB_OFF;         // [2][256]
  uint32_t smem_base = smem_u32(sm);
  uint32_t mbar_base = smem_base + MBAR_OFFB;

  int tid  = threadIdx.x;
  int r    = tid >> 5;                 // 0..15: k-split warp == source chunk rank
  int jl   = tid & 31;
  int bgrp = blockIdx.x >> 4;
  int jt   = blockIdx.x & 15;          // == cluster ctarank (x-linear clustering)
  int j    = jt*32 + jl;
  int k0   = r*32;

  // load recurrent weights for this j-slice into smem
  {
    const float* srcs[3] = {w_hr, w_hz, w_hn};
    #pragma unroll
    for (int g = 0; g < 3; g++) {
      const float* wsrc = srcs[g] + (size_t)j*NH;
      float* wdst = wsm + (g*32 + jl)*WROW;
      #pragma unroll
      for (int kk = 0; kk < 32; kk += 4)
        *(float4*)(wdst + k0 + kk) = *(const float4*)(wsrc + k0 + kk);
    }
  }
  float bhr = b_hr[j], bhz = b_hz[j], bhn = b_hn[j];
  int bb = bgrp*8 + r;                 // epilogue batch (valid r<8)
  float hprev = (r < 8) ? h0[(size_t)bb*NH + j] : 0.f;

  if (tid < 16) {
    asm volatile("mbarrier.init.shared.b64 [%0], %1;" :: "r"(mbar_base + tid*8), "r"(1) : "memory");
  }
  __syncthreads();
  // all mbarriers in the cluster initialized before any arrive can target them
  asm volatile("barrier.cluster.arrive.aligned;" ::: "memory");
  asm volatile("barrier.cluster.wait.aligned;" ::: "memory");

  const float* xr_p = g_x + (size_t)bb*NSTEP*NH + j;
  const float* xz_p = xr_p + (size_t)NBATCH*NSTEP*NH;
  const float* xn_p = xz_p + (size_t)NBATCH*NSTEP*NH;
  float* out_p   = out + (size_t)bb*NSTEP*NH + j;
  float* hlast_p = out + (size_t)NBATCH*NSTEP*NH + (size_t)bb*NH + j;

  const float* wr = wsm + (0*32 + jl)*WROW;
  const float* wz = wsm + (1*32 + jl)*WROW;
  const float* wn = wsm + (2*32 + jl)*WROW;

  // t=0 staging map (from gmem h0): warp r stages chunk h[8b][k0..k0+32)
  int sb = jl >> 2, sc = jl & 3;
  const float4* h0s = (const float4*)(h0 + (size_t)bgrp*8*NH);
  float4* hsm4 = (float4*)hsm;

  uint32_t my_mb = mbar_base + (uint32_t)r*8;

  #pragma unroll 1
  for (int t = 0; t < NSTEP; t++) {
    // prefetch x (epilogue threads)
    float xr = 0.f, xz = 0.f, xn = 0.f;
    if (r < 8) {
      xr = __ldcs(xr_p + (size_t)t*NH);
      xz = __ldcs(xz_p + (size_t)t*NH);
      xn = __ldcs(xn_p + (size_t)t*NH);
    }

    if (t == 0) {
      int i0 = sb*128 + r*8 + sc;
      hsm4[i0]     = __ldcg(h0s + i0);
      hsm4[i0 + 4] = __ldcg(h0s + i0 + 4);
    } else {
      unsigned par = (t - 1) & 1;
      // HW-sleep wait for my chunk's producer (acquire at cluster scope)
      unsigned ok;
      do {
        asm volatile(
          "{\n\t.reg .pred p;\n\t"
          "mbarrier.try_wait.parity.acquire.cluster.shared::cta.b64 p, [%1], %2, 0x989680;\n\t"
          "selp.b32 %0, 1, 0, p;\n\t}"
          : "=r"(ok) : "r"(my_mb), "r"(par) : "memory");
      } while (!ok);
      // pull 1KB chunk from producer rank r's smem h_pub[par]
      uint32_t lp = smem_base + (uint32_t)(PUB_OFF + par*256)*4;
      uint32_t rp;
      asm volatile("mapa.shared::cluster.u32 %0, %1, %2;" : "=r"(rp) : "r"(lp), "r"(r));
      uint32_t a0, a1, a2, a3, c0, c1, c2, c3;
      asm volatile("ld.shared::cluster.v4.b32 {%0,%1,%2,%3}, [%4];"
                   : "=r"(a0), "=r"(a1), "=r"(a2), "=r"(a3) : "r"(rp + (uint32_t)jl*16));
      asm volatile("ld.shared::cluster.v4.b32 {%0,%1,%2,%3}, [%4];"
                   : "=r"(c0), "=r"(c1), "=r"(c2), "=r"(c3) : "r"(rp + (uint32_t)(jl+32)*16));
      int f0 = jl, f1 = jl + 32;
      float4 v0 = make_float4(__uint_as_float(a0), __uint_as_float(a1),
                              __uint_as_float(a2), __uint_as_float(a3));
      float4 v1 = make_float4(__uint_as_float(c0), __uint_as_float(c1),
                              __uint_as_float(c2), __uint_as_float(c3));
      hsm4[(f0>>3)*128 + (k0>>2) + (f0&7)] = v0;
      hsm4[(f1>>3)*128 + (k0>>2) + (f1&7)] = v1;
    }
    __syncwarp();

    // K-split matvec: k in [r*32, r*32+32), 3 gates, 8 batches, packed fp32x2
    u64 ar2[8] = {}, az2[8] = {}, an2[8] = {};
    #pragma unroll 2
    for (int kk = 0; kk < 32; kk += 4) {
      int k = k0 + kk;
      ulonglong2 vr = *(const ulonglong2*)(wr + k);
      ulonglong2 vz = *(const ulonglong2*)(wz + k);
      ulonglong2 vn = *(const ulonglong2*)(wn + k);
      #pragma unroll
      for (int b = 0; b < 8; b++) {
        ulonglong2 hv = *(const ulonglong2*)(hsm + b*NH + k);
        FMA2(ar2[b], vr.x, hv.x); FMA2(ar2[b], vr.y, hv.y);
        FMA2(az2[b], vz.x, hv.x); FMA2(az2[b], vz.y, hv.y);
        FMA2(an2[b], vn.x, hv.x); FMA2(an2[b], vn.y, hv.y);
      }
    }

    float sr[8], sz[8], sn[8];
    #pragma unroll
    for (int b = 0; b < 8; b++) {
      float lo, hi;
      UNPACK2(lo, hi, ar2[b]); sr[b] = lo + hi;
      UNPACK2(lo, hi, az2[b]); sz[b] = lo + hi;
      UNPACK2(lo, hi, an2[b]); sn[b] = lo + hi;
    }
    __syncthreads();                                    // B3: all hsm reads done

    if (r >= 8) {
      int row = (r - 8)*768;
      #pragma unroll
      for (int b = 0; b < 8; b++) {
        part[row +   0 + b*32 + jl] = sr[b];
        part[row + 256 + b*32 + jl] = sz[b];
        part[row + 512 + b*32 + jl] = sn[b];
      }
    }
    __syncthreads();                                    // B4

    if (r < 8) {
      int row = r*768;
      #pragma unroll
      for (int b = 0; b < 8; b++) {
        part[row +   0 + b*32 + jl] += sr[b];
        part[row + 256 + b*32 + jl] += sz[b];
        part[row + 512 + b*32 + jl] += sn[b];
      }
    }
    __syncthreads();                                    // B5

    if (tid < 256) {
      float Sr = 0.f, Sz = 0.f, Sn = 0.f;
      #pragma unroll
      for (int rr = 0; rr < 8; rr++) {
        Sr += part[rr*768 +       tid];
        Sz += part[rr*768 + 256 + tid];
        Sn += part[rr*768 + 512 + tid];
      }
      float rg = 1.f/(1.f + __expf(-(xr + Sr + bhr)));
      float zg = 1.f/(1.f + __expf(-(xz + Sz + bhz)));
      float ng = tanhf(xn + rg*(Sn + bhn));
      float hnew = (1.f - zg)*ng + zg*hprev;
      hprev = hnew;

      __stcs(out_p + (size_t)t*NH, hnew);
      h_pub[(t&1)*256 + tid] = hnew;                    // publish chunk locally
      if (write_hlast && t == NSTEP-1) hlast_p[0] = hnew;

      // epilogue threads done -> signal all cluster CTAs (release.cluster)
      asm volatile("bar.sync 2, 256;" ::: "memory");
      if (tid < 16 && t < NSTEP-1) {
        uint32_t rem;
        asm volatile("mapa.shared::cluster.u32 %0, %1, %2;"
                     : "=r"(rem) : "r"(mbar_base + (uint32_t)jt*8), "r"(tid));
        asm volatile("mbarrier.arrive.release.cluster.shared::cluster.b64 _, [%0];"
                     :: "r"(rem) : "memory");
      }
    }

    __syncthreads();   // B6: part reads done before next step's hsm staging overlays it
  }

  // no CTA may exit while peers might still read its smem / arrive on its mbarriers
  asm volatile("barrier.cluster.arrive.aligned;" ::: "memory");
  asm volatile("barrier.cluster.wait.aligned;" ::: "memory");
}

extern "C" void kernel_launch(void* const* d_in, const int* in_sizes, int n_in,
                              void* d_out, int out_size) {
  const float* inp  = (const float*)d_in[0];
  const float* h0   = (const float*)d_in[1];
  const float* w_ir = (const float*)d_in[2];
  const float* w_iz = (const float*)d_in[3];
  const float* w_in = (const float*)d_in[4];
  const float* b_ir = (const float*)d_in[5];
  const float* b_iz = (const float*)d_in[6];
  const float* b_in = (const float*)d_in[7];
  const float* w_hr = (const float*)d_in[8];
  const float* w_hz = (const float*)d_in[9];
  const float* w_hn = (const float*)d_in[10];
  const float* b_hr = (const float*)d_in[11];
  const float* b_hz = (const float*)d_in[12];
  const float* b_hn = (const float*)d_in[13];
  float* out = (float*)d_out;

  cudaFuncSetAttribute(gru_rec, cudaFuncAttributeMaxDynamicSharedMemorySize, SMEM_BYTES);
  cudaFuncSetAttribute(gru_rec, cudaFuncAttributeNonPortableClusterSizeAllowed, 1);

  dim3 gg(NH/64, (NBATCH*NSTEP)/64, 3);
  xproj_kernel<<<gg, 256>>>(inp, w_ir, w_iz, w_in, b_ir, b_iz, b_in);

  int write_hlast = (out_size >= NBATCH*NSTEP*NH + NBATCH*NH) ? 1 : 0;

  cudaLaunchConfig_t cfg = {};
  cfg.gridDim  = dim3(128, 1, 1);
  cfg.blockDim = dim3(512, 1, 1);
  cfg.dynamicSmemBytes = SMEM_BYTES;
  cfg.stream = 0;
  cudaLaunchAttribute attrs[1];
  attrs[0].id = cudaLaunchAttributeClusterDimension;
  attrs[0].val.clusterDim.x = 16;
  attrs[0].val.clusterDim.y = 1;
  attrs[0].val.clusterDim.z = 1;
  cfg.attrs = attrs;
  cfg.numAttrs = 1;

  cudaLaunchKernelEx(&cfg, gru_rec, h0, w_hr, w_hz, w_hn, b_hr, b_hz, b_hn,
                     out, write_hlast);
}

// round 12
// speedup vs baseline: 1.4679x; 1.4679x over previous
#include <cuda_runtime.h>
#include <math.h>
#include <stdint.h>

#define NBATCH 64
#define NSTEP  1024
#define NIN    256
#define NH     512

// smem floats: wsm [3][32][512] swizzled | hsm [2][4][512] | part [8][384] | done[32]
#define WS_OFF   0
#define HS_OFF   (3*32*512)                 // 49152
#define PT_OFF   (HS_OFF + 2*4*512)         // 53248
#define DONE_OFF (PT_OFF + 8*384)           // 56320
#define SMEM_FLOATS (DONE_OFF + 32)
#define SMEM_BYTES  (SMEM_FLOATS*4)         // 225,408 B

typedef unsigned long long u64;

#define FMA2(acc, a, b) asm("fma.rn.f32x2 %0, %1, %2, %0;" : "+l"(acc) : "l"(a), "l"(b))
#define DUP2(r, x)      asm("mov.b64 %0, {%1, %1};" : "=l"(r) : "f"(x))
#define UNPACK2(lo, hi, v) asm("mov.b64 {%0, %1}, %2;" : "=f"(lo), "=f"(hi) : "l"(v))

__device__ float    g_x[(size_t)3*NBATCH*NSTEP*NH];   // input projections
__device__ float    g_h[2*NBATCH*NH];
__device__ unsigned g_flags[256];                      // [16 groups][16 jt]

__device__ __forceinline__ unsigned ld_acq(const unsigned* p) {
  unsigned v;
  asm volatile("ld.global.acquire.gpu.b32 %0, [%1];" : "=r"(v) : "l"(p) : "memory");
  return v;
}
__device__ __forceinline__ void st_rel(unsigned* p, unsigned v) {
  asm volatile("st.global.release.gpu.b32 [%0], %1;" :: "l"(p), "r"(v) : "memory");
}
__device__ __forceinline__ unsigned ld_acq_sh(const unsigned* p) {
  unsigned v;
  asm volatile("ld.acquire.cta.b32 %0, [%1];" : "=r"(v) : "l"(p) : "memory");
  return v;
}
__device__ __forceinline__ void st_rel_sh(unsigned* p, unsigned v) {
  asm volatile("st.release.cta.b32 [%0], %1;" :: "l"(p), "r"(v) : "memory");
}

// ---------------- input projection GEMM ----------------
__global__ void __launch_bounds__(256) xproj_kernel(
    const float* __restrict__ A,
    const float* __restrict__ w0, const float* __restrict__ w1, const float* __restrict__ w2,
    const float* __restrict__ b0, const float* __restrict__ b1, const float* __restrict__ b2)
{
  __shared__ float As[32][68];
  __shared__ float Bs[32][68];

  int tid = threadIdx.x;
  if (blockIdx.x == 0 && blockIdx.y == 0 && blockIdx.z == 0)
    g_flags[tid] = 0u;   // 256 threads reset 256 flags

  int g = blockIdx.z;
  const float* W    = (g==0) ? w0 : ((g==1) ? w1 : w2);
  const float* bias = (g==0) ? b0 : ((g==1) ? b1 : b2);
  float* C = g_x + (size_t)g * (size_t)(NBATCH*NSTEP) * NH;

  int m0 = blockIdx.y * 64;
  int n0 = blockIdx.x * 64;
  int tx = tid & 15, ty = tid >> 4;
  int lr = tid >> 3;
  int lc = (tid & 7) * 4;

  u64 acc2[4][2] = {};

  for (int k0 = 0; k0 < NIN; k0 += 32) {
    float4 a0 = *(const float4*)(A + (size_t)(m0+lr   )*NIN + k0 + lc);
    float4 a1 = *(const float4*)(A + (size_t)(m0+lr+32)*NIN + k0 + lc);
    float4 v0 = *(const float4*)(W + (size_t)(n0+lr   )*NIN + k0 + lc);
    float4 v1 = *(const float4*)(W + (size_t)(n0+lr+32)*NIN + k0 + lc);
    __syncthreads();
    As[lc+0][lr] = a0.x; As[lc+1][lr] = a0.y; As[lc+2][lr] = a0.z; As[lc+3][lr] = a0.w;
    As[lc+0][lr+32] = a1.x; As[lc+1][lr+32] = a1.y; As[lc+2][lr+32] = a1.z; As[lc+3][lr+32] = a1.w;
    Bs[lc+0][lr] = v0.x; Bs[lc+1][lr] = v0.y; Bs[lc+2][lr] = v0.z; Bs[lc+3][lr] = v0.w;
    Bs[lc+0][lr+32] = v1.x; Bs[lc+1][lr+32] = v1.y; Bs[lc+2][lr+32] = v1.z; Bs[lc+3][lr+32] = v1.w;
    __syncthreads();
    #pragma unroll
    for (int kk = 0; kk < 32; kk++) {
      float4 av = *(const float4*)(&As[kk][ty*4]);
      ulonglong2 bp = *(const ulonglong2*)(&Bs[kk][tx*4]);
      u64 d0, d1, d2, d3;
      DUP2(d0, av.x); DUP2(d1, av.y); DUP2(d2, av.z); DUP2(d3, av.w);
      FMA2(acc2[0][0], d0, bp.x); FMA2(acc2[0][1], d0, bp.y);
      FMA2(acc2[1][0], d1, bp.x); FMA2(acc2[1][1], d1, bp.y);
      FMA2(acc2[2][0], d2, bp.x); FMA2(acc2[2][1], d2, bp.y);
      FMA2(acc2[3][0], d3, bp.x); FMA2(acc2[3][1], d3, bp.y);
    }
  }

  float4 bv = *(const float4*)(bias + n0 + tx*4);
  #pragma unroll
  for (int i = 0; i < 4; i++) {
    int row = m0 + ty*4 + i;
    float c0, c1, c2, c3;
    UNPACK2(c0, c1, acc2[i][0]);
    UNPACK2(c2, c3, acc2[i][1]);
    float4 o;
    o.x = c0 + bv.x; o.y = c1 + bv.y;
    o.z = c2 + bv.z; o.w = c3 + bv.w;
    *(float4*)(C + (size_t)row*NH + n0 + tx*4) = o;
  }
}

// ---------------- persistent GRU recurrence: 2 interleaved chains per CTA ----------------
// 128 CTAs = 16 j-tiles x 8 CTA-rows (m). CTA (m, jt) runs TWO independent 4-batch
// recurrence chains: group gA=2m (batches 8m..8m+3) and gB=2m+1 (batches 8m+4..8m+7),
// both over cols [jt*32,+32) with the SAME smem-resident weights. Phase A's inter-CTA
// handshake (release -> poller -> L2 h pull) is hidden behind phase B's compute.
// 544 threads: warps 0..15 workers (k-split 16), warp 16 = L2 flag poller for 32 flags.
__global__ void __launch_bounds__(544, 1) gru_rec(
    const float* __restrict__ h0,
    const float* __restrict__ w_hr, const float* __restrict__ w_hz, const float* __restrict__ w_hn,
    const float* __restrict__ b_hr, const float* __restrict__ b_hz, const float* __restrict__ b_hn,
    float* __restrict__ out, int write_hlast)
{
  extern __shared__ float sm[];
  float* wsm  = sm + WS_OFF;                 // [3][32][512], float4-XOR swizzled
  float* hsm  = sm + HS_OFF;                 // [2 chains][4][512]
  float* part = sm + PT_OFF;                 // [8][384]
  unsigned* done = (unsigned*)(sm + DONE_OFF);  // [32] = [2 chains][16]

  int tid  = threadIdx.x;
  int r    = tid >> 5;                 // 0..15 worker k-split; 16 = poller
  int jl   = tid & 31;
  int m    = blockIdx.x >> 4;          // 0..7
  int jt   = blockIdx.x & 15;
  int j    = jt*32 + jl;
  int k0   = r*32;
  int sw   = (jl & 7);                 // float4 swizzle key for this col

  if (tid < 512) {
    // weights: wsm[g][jl][k], float4 index k16 stored at (k16 ^ (jl&7))
    const float* srcs[3] = {w_hr, w_hz, w_hn};
    #pragma unroll
    for (int g = 0; g < 3; g++) {
      const float* wsrc = srcs[g] + (size_t)j*NH;
      float* wdst = wsm + (g*32 + jl)*512;
      #pragma unroll
      for (int kk = 0; kk < 32; kk += 4) {
        int k16 = (k0 + kk) >> 2;
        *(float4*)(wdst + ((k16 ^ sw) << 2)) = *(const float4*)(wsrc + k0 + kk);
      }
    }
  }
  if (tid < 32) done[tid] = 0u;
  __syncthreads();   // all 544

  // ---- poller warp: 32 lanes <-> 32 flags (two groups of this CTA-row) ----
  if (r == 16) {
    if (jl < 32) {
      const unsigned* fp = g_flags + m*32 + jl;
      unsigned* dp = done + jl;
      unsigned last = 0u;
      while (last < (unsigned)NSTEP) {
        unsigned v = ld_acq(fp);
        if (v > last) { last = v; st_rel_sh(dp, v); }
        else __nanosleep(40);
      }
    }
    return;
  }

  // ---- workers ----
  float bhr = b_hr[j], bhz = b_hz[j], bhn = b_hn[j];

  const float* wr = wsm + (0*32 + jl)*512;
  const float* wz = wsm + (1*32 + jl)*512;
  const float* wn = wsm + (2*32 + jl)*512;

  // per-chain epilogue state (threads < 128: b = tid>>5 in 0..3)
  int eb = tid >> 5;                    // 0..3 for epilogue threads
  float hprev[2];
  const float* xp[2][3];
  float* outp[2];
  float* hlastp[2];
  unsigned* flagp[2];
  #pragma unroll
  for (int c = 0; c < 2; c++) {
    int gidx = 2*m + c;
    int bb = gidx*4 + eb;
    hprev[c] = (tid < 128) ? h0[(size_t)bb*NH + j] : 0.f;
    xp[c][0] = g_x + (size_t)bb*NSTEP*NH + j;
    xp[c][1] = xp[c][0] + (size_t)NBATCH*NSTEP*NH;
    xp[c][2] = xp[c][1] + (size_t)NBATCH*NSTEP*NH;
    outp[c]  = out + (size_t)bb*NSTEP*NH + j;
    hlastp[c] = out + (size_t)NBATCH*NSTEP*NH + (size_t)bb*NH + j;
    flagp[c] = g_flags + m*32 + c*16 + jt;
  }

  // staging map: warp r stages chunk h[4b][k0..+32) = 32 float4, 1 per lane
  int sb = jl >> 3, sc = jl & 7;       // batch 0..3, float4 sub
  int sidx = sb*128 + r*8 + sc;

  #pragma unroll 1
  for (int t = 0; t < NSTEP; t++) {
    // prefetch both chains' x contributions (DRAM, overlapped)
    float xv[2][3];
    if (tid < 128) {
      #pragma unroll
      for (int c = 0; c < 2; c++) {
        xv[c][0] = __ldcs(xp[c][0] + (size_t)t*NH);
        xv[c][1] = __ldcs(xp[c][1] + (size_t)t*NH);
        xv[c][2] = __ldcs(xp[c][2] + (size_t)t*NH);
      }
    }

    #pragma unroll
    for (int c = 0; c < 2; c++) {
      // per-warp wait on local done flag for my source chunk of this chain
      if (t > 0) {
        const unsigned* dp = done + c*16 + r;
        if (ld_acq_sh(dp) < (unsigned)t) {
          while (ld_acq_sh(dp) < (unsigned)t) __nanosleep(20);
        }
      }

      // stage my chunk (warp-private: same warp writes & reads)
      float* hc = hsm + c*2048;
      {
        const float4* src = (t == 0)
          ? (const float4*)(h0 + (size_t)(2*m + c)*4*NH)
          : (const float4*)(g_h + (size_t)((t-1)&1)*NBATCH*NH + (size_t)(2*m + c)*4*NH);
        ((float4*)hc)[sidx] = __ldcg(src + sidx);
      }
      __syncwarp();

      // matvec: k in [k0, k0+32), 3 gates, 4 batches, packed fp32x2
      u64 ar2[4] = {}, az2[4] = {}, an2[4] = {};
      #pragma unroll
      for (int kk8 = 0; kk8 < 8; kk8++) {
        int k16 = r*8 + kk8;
        int s4 = (k16 ^ sw) << 2;
        int k  = k0 + kk8*4;
        ulonglong2 vr = *(const ulonglong2*)(wr + s4);
        ulonglong2 vz = *(const ulonglong2*)(wz + s4);
        ulonglong2 vn = *(const ulonglong2*)(wn + s4);
        #pragma unroll
        for (int b = 0; b < 4; b++) {
          ulonglong2 hv = *(const ulonglong2*)(hc + b*NH + k);
          FMA2(ar2[b], vr.x, hv.x); FMA2(ar2[b], vr.y, hv.y);
          FMA2(az2[b], vz.x, hv.x); FMA2(az2[b], vz.y, hv.y);
          FMA2(an2[b], vn.x, hv.x); FMA2(an2[b], vn.y, hv.y);
        }
      }
      float sr[4], sz[4], sn[4];
      #pragma unroll
      for (int b = 0; b < 4; b++) {
        float lo, hi;
        UNPACK2(lo, hi, ar2[b]); sr[b] = lo + hi;
        UNPACK2(lo, hi, az2[b]); sz[b] = lo + hi;
        UNPACK2(lo, hi, an2[b]); sn[b] = lo + hi;
      }

      // part is free only after previous phase's epilogue finished reading it
      asm volatile("bar.sync 1, 512;" ::: "memory");

      if (r >= 8) {
        int row = (r - 8)*384;
        #pragma unroll
        for (int b = 0; b < 4; b++) {
          part[row +   0 + b*32 + jl] = sr[b];
          part[row + 128 + b*32 + jl] = sz[b];
          part[row + 256 + b*32 + jl] = sn[b];
        }
      }
      asm volatile("bar.sync 1, 512;" ::: "memory");

      if (r < 8) {
        int row = r*384;
        #pragma unroll
        for (int b = 0; b < 4; b++) {
          part[row +   0 + b*32 + jl] += sr[b];
          part[row + 128 + b*32 + jl] += sz[b];
          part[row + 256 + b*32 + jl] += sn[b];
        }
      }
      asm volatile("bar.sync 1, 512;" ::: "memory");

      if (tid < 128) {
        float Sr = 0.f, Sz = 0.f, Sn = 0.f;
        #pragma unroll
        for (int rr = 0; rr < 8; rr++) {
          Sr += part[rr*384 +       tid];
          Sz += part[rr*384 + 128 + tid];
          Sn += part[rr*384 + 256 + tid];
        }
        float rg = 1.f/(1.f + __expf(-(xv[c][0] + Sr + bhr)));
        float zg = 1.f/(1.f + __expf(-(xv[c][1] + Sz + bhz)));
        float ng = tanhf(xv[c][2] + rg*(Sn + bhn));
        float hnew = (1.f - zg)*ng + zg*hprev[c];
        hprev[c] = hnew;

        int bb = (2*m + c)*4 + eb;
        __stcg(&g_h[(size_t)(t&1)*NBATCH*NH + (size_t)bb*NH + j], hnew);

        // all 128 epilogue threads' h stores done -> release ASAP
        asm volatile("bar.sync 2, 128;" ::: "memory");
        if (tid == 0) {
          st_rel(flagp[c], (unsigned)(t+1));
          st_rel_sh(done + c*16 + jt, (unsigned)(t+1));
        }

        // non-critical stores after the release
        __stcs(outp[c] + (size_t)t*NH, hnew);
        if (write_hlast && t == NSTEP-1) hlastp[c][0] = hnew;
      }
      // (no trailing CTA barrier: next phase's pre-dump bar.sync 1 orders
      //  this epilogue's part reads before the next dump's part writes)
    }
  }
}

extern "C" void kernel_launch(void* const* d_in, const int* in_sizes, int n_in,
                              void* d_out, int out_size) {
  const float* inp  = (const float*)d_in[0];
  const float* h0   = (const float*)d_in[1];
  const float* w_ir = (const float*)d_in[2];
  const float* w_iz = (const float*)d_in[3];
  const float* w_in = (const float*)d_in[4];
  const float* b_ir = (const float*)d_in[5];
  const float* b_iz = (const float*)d_in[6];
  const float* b_in = (const float*)d_in[7];
  const float* w_hr = (const float*)d_in[8];
  const float* w_hz = (const float*)d_in[9];
  const float* w_hn = (const float*)d_in[10];
  const float* b_hr = (const float*)d_in[11];
  const float* b_hz = (const float*)d_in[12];
  const float* b_hn = (const float*)d_in[13];
  float* out = (float*)d_out;

  cudaFuncSetAttribute(gru_rec, cudaFuncAttributeMaxDynamicSharedMemorySize, SMEM_BYTES);

  dim3 gg(NH/64, (NBATCH*NSTEP)/64, 3);
  xproj_kernel<<<gg, 256>>>(inp, w_ir, w_iz, w_in, b_ir, b_iz, b_in);

  int write_hlast = (out_size >= NBATCH*NSTEP*NH + NBATCH*NH) ? 1 : 0;
  gru_rec<<<128, 544, SMEM_BYTES>>>(h0, w_hr, w_hz, w_hn, b_hr, b_hz, b_hn,
                                    out, write_hlast);
}